// round 11
// baseline (speedup 1.0000x reference)
#include <cuda_runtime.h>
#include <cstdint>

typedef unsigned long long ull;

// ---------- packed f32x2 helpers (sm_103a) ----------
__device__ __forceinline__ ull pack2(float a, float b) {
    ull r; asm("mov.b64 %0, {%1, %2};" : "=l"(r) : "f"(a), "f"(b)); return r;
}
__device__ __forceinline__ void unpack2(ull v, float& a, float& b) {
    asm("mov.b64 {%0, %1}, %2;" : "=f"(a), "=f"(b) : "l"(v));
}
__device__ __forceinline__ ull ffma2(ull a, ull b, ull c) {
    ull d; asm("fma.rn.f32x2 %0, %1, %2, %3;" : "=l"(d) : "l"(a), "l"(b), "l"(c)); return d;
}
__device__ __forceinline__ ull relu2(ull v) {
    float a, b; unpack2(v, a, b);
    return pack2(fmaxf(a, 0.f), fmaxf(b, 0.f));
}
#define DUP(f) pack2((f), (f))   // 1 ALU op: duplicate scalar weight into both halves

#define NJ 24
#define JWF 104         // floats per joint: 13 rows x 8 (7 weights + bias), NON-dup
#define WPB 18          // warps per block
#define XPAD 25         // x slab row stride in floats (odd -> conflict-free scalar LDS)
#define TPAD 22         // eighth-tile row stride (22l mod 32 distinct per 16-lane phase)
#define XSLAB_BYTES (64 * XPAD * 4)              // 6400
#define TILE_BYTES  (64 * TPAD * 4)              // 5632
#define WARP_BYTES  (XSLAB_BYTES + TILE_BYTES)   // 12032
#define SW_BYTES (NJ * JWF * 4)                  // 9984
#define SMEM_BYTES (SW_BYTES + WPB * WARP_BYTES) // 226560

// ---- full joint: 7x7 layer1 + 6x7 layer2, non-dup weights (float4 view) ----
__device__ __forceinline__ void joint_fwd(const float4* wp, ull xp,
                                          const ull* pf, ull* fo) {
    ull h[7];
#pragma unroll
    for (int o = 0; o < 7; ++o) {
        float4 wa = wp[o * 2], wb = wp[o * 2 + 1];   // w0..w3 | w4,w5,w6,bias
        ull acc = ffma2(DUP(wa.x), xp, DUP(wb.w));
        acc = ffma2(DUP(wa.y), pf[0], acc);
        acc = ffma2(DUP(wa.z), pf[1], acc);
        acc = ffma2(DUP(wa.w), pf[2], acc);
        acc = ffma2(DUP(wb.x), pf[3], acc);
        acc = ffma2(DUP(wb.y), pf[4], acc);
        acc = ffma2(DUP(wb.z), pf[5], acc);
        h[o] = relu2(acc);
    }
#pragma unroll
    for (int o = 0; o < 6; ++o) {
        float4 wa = wp[14 + o * 2], wb = wp[14 + o * 2 + 1];
        ull acc = ffma2(DUP(wa.x), h[0], DUP(wb.w));
        acc = ffma2(DUP(wa.y), h[1], acc);
        acc = ffma2(DUP(wa.z), h[2], acc);
        acc = ffma2(DUP(wa.w), h[3], acc);
        acc = ffma2(DUP(wb.x), h[4], acc);
        acc = ffma2(DUP(wb.y), h[5], acc);
        acc = ffma2(DUP(wb.z), h[6], acc);
        fo[o] = relu2(acc);
    }
}

// root: parent features are zero
__device__ __forceinline__ void root_fwd(const float4* wp, ull xp, ull* fo) {
    ull h[7];
#pragma unroll
    for (int o = 0; o < 7; ++o) {
        float4 wa = wp[o * 2], wb = wp[o * 2 + 1];
        h[o] = relu2(ffma2(DUP(wa.x), xp, DUP(wb.w)));
    }
#pragma unroll
    for (int o = 0; o < 6; ++o) {
        float4 wa = wp[14 + o * 2], wb = wp[14 + o * 2 + 1];
        ull acc = ffma2(DUP(wa.x), h[0], DUP(wb.w));
        acc = ffma2(DUP(wa.y), h[1], acc);
        acc = ffma2(DUP(wa.z), h[2], acc);
        acc = ffma2(DUP(wa.w), h[3], acc);
        acc = ffma2(DUP(wb.x), h[4], acc);
        acc = ffma2(DUP(wb.y), h[5], acc);
        acc = ffma2(DUP(wb.z), h[6], acc);
        fo[o] = relu2(acc);
    }
}

// store 6 packed values: lows -> row ra, highs -> row rb (aligned float2)
__device__ __forceinline__ void store6(const ull* f, float* ra, float* rb, int cb) {
    float a0,b0,a1,b1,a2,b2,a3,b3,a4,b4,a5,b5;
    unpack2(f[0], a0, b0); unpack2(f[1], a1, b1); unpack2(f[2], a2, b2);
    unpack2(f[3], a3, b3); unpack2(f[4], a4, b4); unpack2(f[5], a5, b5);
    ((float2*)(ra + cb))[0] = make_float2(a0, a1);
    ((float2*)(ra + cb))[1] = make_float2(a2, a3);
    ((float2*)(ra + cb))[2] = make_float2(a4, a5);
    ((float2*)(rb + cb))[0] = make_float2(b0, b1);
    ((float2*)(rb + cb))[1] = make_float2(b2, b3);
    ((float2*)(rb + cb))[2] = make_float2(b4, b5);
}

__global__ void __launch_bounds__(WPB * 32)
StructureEncoder1D_kernel(const float* __restrict__ x,
                          const float* __restrict__ W1,
                          const float* __restrict__ b1,
                          const float* __restrict__ W2,
                          const float* __restrict__ b2,
                          float* __restrict__ out, int B) {
    extern __shared__ __align__(16) char dynsmem[];
    float* sw    = reinterpret_cast<float*>(dynsmem);                // non-dup weights
    char*  wbase = dynsmem + SW_BYTES;

    // ---- cooperative weight fill (plain floats, rows of 8) ----
    for (int i = threadIdx.x; i < NJ * JWF; i += blockDim.x) {
        int j = i / JWF, r = i % JWF, row = r >> 3, c = r & 7;
        float v;
        if (row < 7) {
            v = (c < 7) ? W1[j * 49 + row * 7 + c] : b1[j * 7 + row];
        } else {
            int rr = row - 7;
            v = (c < 7) ? W2[j * 42 + rr * 7 + c] : b2[j * 6 + rr];
        }
        sw[i] = v;
    }
    __syncthreads();

    const int lane   = threadIdx.x & 31;
    const int warpId = threadIdx.x >> 5;
    const int warpBase = (blockIdx.x * WPB + warpId) * 64;
    if (warpBase >= B) return;

    char* wb = wbase + warpId * WARP_BYTES;
    float* xslab = reinterpret_cast<float*>(wb);                 // persistent x
    float* tile  = reinterpret_cast<float*>(wb + XSLAB_BYTES);   // output tile

    // ---- stage x: coalesced LDG.128 -> xslab (row stride 25 floats) ----
    {
        const float4* xin = reinterpret_cast<const float4*>(x);
#pragma unroll
        for (int k = 0; k < 12; ++k) {
            int i = k * 32 + lane;               // [0,384): 64 rows x 6 float4
            int r = i / 6, c = i % 6;
            float4 v = make_float4(0.f, 0.f, 0.f, 0.f);
            if (warpBase + r < B) v = xin[(size_t)(warpBase + r) * 6 + c];
            float* d = xslab + r * XPAD + c * 4;
            d[0] = v.x; d[1] = v.y; d[2] = v.z; d[3] = v.w;
        }
    }
    __syncwarp();

    float* ta = tile + lane * TPAD;          // even offset -> aligned float2
    float* tb = tile + (lane + 32) * TPAD;

    ull fA[6], fB[6], fC[6];

#define XP(J) pack2(xslab[lane * XPAD + (J)], xslab[(lane + 32) * XPAD + (J)])
#define WP(J) (reinterpret_cast<const float4*>(sw) + (J) * 26)
#define ST(F, CB) store6(F, ta, tb, CB)

    // flush eighth tile: 64 rows x 18 cols -> out cols [G*18, G*18+18)
#define FLUSH(G) do {                                                          \
        __syncwarp();                                                          \
        _Pragma("unroll")                                                      \
        for (int k = 0; k < 18; ++k) {                                         \
            int i = k * 32 + lane;               /* [0,576): 64 rows x 9 f2 */ \
            int r = i / 9, c = i % 9;                                          \
            if (warpBase + r < B) {                                            \
                float2 v = *reinterpret_cast<const float2*>(                   \
                    tile + r * TPAD + c * 2);                                  \
                *reinterpret_cast<float2*>(                                    \
                    out + (size_t)(warpBase + r) * 144 + (G) * 18 + c * 2) = v;\
            }                                                                  \
        }                                                                      \
        __syncwarp();                                                          \
    } while (0)

    // ---- phase 0: {0,1,2} ----
    root_fwd (WP(0), XP(0),      fA);  ST(fA, 0);    // fA = f0
    joint_fwd(WP(1), XP(1), fA,  fB);  ST(fB, 6);    // fB = f1
    joint_fwd(WP(2), XP(2), fA,  fC);  ST(fC, 12);   // fC = f2
    FLUSH(0);
    // ---- phase 1: {3,4,5}  (fA=f0, fB=f1, fC=f2) ----
    joint_fwd(WP(3), XP(3), fA,  fA);  ST(fA, 0);    // fA = f3
    joint_fwd(WP(4), XP(4), fB,  fB);  ST(fB, 6);    // fB = f4
    joint_fwd(WP(5), XP(5), fC,  fC);  ST(fC, 12);   // fC = f5
    FLUSH(1);
    // ---- phase 2: {6,7,8}  (fA=f3, fB=f4, fC=f5) ----
    joint_fwd(WP(6), XP(6), fA,  fA);  ST(fA, 0);    // fA = f6
    joint_fwd(WP(7), XP(7), fB,  fB);  ST(fB, 6);    // fB = f7
    joint_fwd(WP(8), XP(8), fC,  fC);  ST(fC, 12);   // fC = f8
    FLUSH(2);
    // ---- phase 3: {9,10,11}  (fA=f6, fB=f7, fC=f8) ----
    joint_fwd(WP(9),  XP(9),  fA, fA); ST(fA, 0);    // fA = f9
    joint_fwd(WP(10), XP(10), fB, fB); ST(fB, 6);    // f10 (leaf)
    joint_fwd(WP(11), XP(11), fC, fC); ST(fC, 12);   // f11 (leaf)
    FLUSH(3);
    // ---- phase 4: {12,13,14}  (fA=f9, parents of 12,13,14 all = 9) ----
    joint_fwd(WP(12), XP(12), fA, fB); ST(fB, 0);    // fB = f12
    joint_fwd(WP(13), XP(13), fA, fC); ST(fC, 6);    // fC = f13
    joint_fwd(WP(14), XP(14), fA, fA); ST(fA, 12);   // fA = f14
    FLUSH(4);
    // ---- phase 5: {15,16,17}  (fB=f12, fC=f13, fA=f14) ----
    joint_fwd(WP(15), XP(15), fB, fB); ST(fB, 0);    // f15 (leaf)
    joint_fwd(WP(16), XP(16), fC, fC); ST(fC, 6);    // fC = f16
    joint_fwd(WP(17), XP(17), fA, fA); ST(fA, 12);   // fA = f17
    FLUSH(5);
    // ---- phase 6: {18,19,20}  (fC=f16, fA=f17; 18<-16, 19<-17, 20<-18) ----
    joint_fwd(WP(18), XP(18), fC, fB); ST(fB, 0);    // fB = f18
    joint_fwd(WP(19), XP(19), fA, fA); ST(fA, 6);    // fA = f19
    joint_fwd(WP(20), XP(20), fB, fB); ST(fB, 12);   // fB = f20
    FLUSH(6);
    // ---- phase 7: {21,22,23}  (fA=f19, fB=f20; 21<-19, 22<-20, 23<-21) ----
    joint_fwd(WP(21), XP(21), fA, fC); ST(fC, 0);    // fC = f21
    joint_fwd(WP(22), XP(22), fB, fB); ST(fB, 6);    // f22 (leaf)
    joint_fwd(WP(23), XP(23), fC, fC); ST(fC, 12);   // f23 (leaf)
    FLUSH(7);

#undef XP
#undef WP
#undef ST
#undef FLUSH
}

extern "C" void kernel_launch(void* const* d_in, const int* in_sizes, int n_in,
                              void* d_out, int out_size) {
    const float* x  = (const float*)d_in[0];
    const float* W1 = (const float*)d_in[1];
    const float* b1 = (const float*)d_in[2];
    const float* W2 = (const float*)d_in[3];
    const float* b2 = (const float*)d_in[4];
    float* out = (float*)d_out;

    int B = in_sizes[0] / 24;
    int warps  = (B + 63) / 64;
    int blocks = (warps + WPB - 1) / WPB;

    cudaFuncSetAttribute(StructureEncoder1D_kernel,
                         cudaFuncAttributeMaxDynamicSharedMemorySize, SMEM_BYTES);
    StructureEncoder1D_kernel<<<blocks, WPB * 32, SMEM_BYTES>>>(x, W1, b1, W2, b2, out, B);
}

// round 12
// speedup vs baseline: 1.3791x; 1.3791x over previous
#include <cuda_runtime.h>
#include <cstdint>

typedef unsigned long long ull;

// ---------- packed f32x2 helpers (sm_103a) ----------
__device__ __forceinline__ ull pack2(float a, float b) {
    ull r; asm("mov.b64 %0, {%1, %2};" : "=l"(r) : "f"(a), "f"(b)); return r;
}
__device__ __forceinline__ void unpack2(ull v, float& a, float& b) {
    asm("mov.b64 {%0, %1}, %2;" : "=f"(a), "=f"(b) : "l"(v));
}
__device__ __forceinline__ ull ffma2(ull a, ull b, ull c) {
    ull d; asm("fma.rn.f32x2 %0, %1, %2, %3;" : "=l"(d) : "l"(a), "l"(b), "l"(c)); return d;
}
__device__ __forceinline__ ull relu2(ull v) {
    float a, b; unpack2(v, a, b);
    return pack2(fmaxf(a, 0.f), fmaxf(b, 0.f));
}
#define DUP(f) pack2((f), (f))   // 1 ALU op: duplicate scalar weight into both halves

#define NJ 24
#define JWF 104         // floats per joint: 13 rows x 8 (7 weights + bias), NON-dup
#define WPB 14          // warps per block (single change vs R10: 12 -> 14)
#define TPAD 38         // quarter-tile row stride in floats (even; stride-6 banks conflict-free)
#define TILE_FLOATS (64 * TPAD)                  // 9728 B
#define XS_ULL (24 * 32)                         // packed-x per warp: 6144 B
#define SW_BYTES (NJ * JWF * 4)                  // 9984
#define WARP_BYTES (XS_ULL * 8 + TILE_FLOATS * 4)          // 15872
#define SMEM_BYTES (SW_BYTES + WPB * WARP_BYTES)           // 232192 <= 232448

// ---- full joint: 7x7 layer1 + 6x7 layer2, non-dup weights (float4 view) ----
__device__ __forceinline__ void joint_fwd(const float4* wp, ull xp,
                                          const ull* pf, ull* fo) {
    ull h[7];
#pragma unroll
    for (int o = 0; o < 7; ++o) {
        float4 wa = wp[o * 2], wb = wp[o * 2 + 1];   // w0..w3 | w4,w5,w6,bias
        ull acc = ffma2(DUP(wa.x), xp, DUP(wb.w));
        acc = ffma2(DUP(wa.y), pf[0], acc);
        acc = ffma2(DUP(wa.z), pf[1], acc);
        acc = ffma2(DUP(wa.w), pf[2], acc);
        acc = ffma2(DUP(wb.x), pf[3], acc);
        acc = ffma2(DUP(wb.y), pf[4], acc);
        acc = ffma2(DUP(wb.z), pf[5], acc);
        h[o] = relu2(acc);
    }
#pragma unroll
    for (int o = 0; o < 6; ++o) {
        float4 wa = wp[14 + o * 2], wb = wp[14 + o * 2 + 1];
        ull acc = ffma2(DUP(wa.x), h[0], DUP(wb.w));
        acc = ffma2(DUP(wa.y), h[1], acc);
        acc = ffma2(DUP(wa.z), h[2], acc);
        acc = ffma2(DUP(wa.w), h[3], acc);
        acc = ffma2(DUP(wb.x), h[4], acc);
        acc = ffma2(DUP(wb.y), h[5], acc);
        acc = ffma2(DUP(wb.z), h[6], acc);
        fo[o] = relu2(acc);
    }
}

// root: parent features are zero
__device__ __forceinline__ void root_fwd(const float4* wp, ull xp, ull* fo) {
    ull h[7];
#pragma unroll
    for (int o = 0; o < 7; ++o) {
        float4 wa = wp[o * 2], wb = wp[o * 2 + 1];
        h[o] = relu2(ffma2(DUP(wa.x), xp, DUP(wb.w)));
    }
#pragma unroll
    for (int o = 0; o < 6; ++o) {
        float4 wa = wp[14 + o * 2], wb = wp[14 + o * 2 + 1];
        ull acc = ffma2(DUP(wa.x), h[0], DUP(wb.w));
        acc = ffma2(DUP(wa.y), h[1], acc);
        acc = ffma2(DUP(wa.z), h[2], acc);
        acc = ffma2(DUP(wa.w), h[3], acc);
        acc = ffma2(DUP(wb.x), h[4], acc);
        acc = ffma2(DUP(wb.y), h[5], acc);
        acc = ffma2(DUP(wb.z), h[6], acc);
        fo[o] = relu2(acc);
    }
}

// store 6 packed values: lows -> row ra, highs -> row rb (aligned float2)
__device__ __forceinline__ void store6(const ull* f, float* ra, float* rb, int cb) {
    float a0,b0,a1,b1,a2,b2,a3,b3,a4,b4,a5,b5;
    unpack2(f[0], a0, b0); unpack2(f[1], a1, b1); unpack2(f[2], a2, b2);
    unpack2(f[3], a3, b3); unpack2(f[4], a4, b4); unpack2(f[5], a5, b5);
    ((float2*)(ra + cb))[0] = make_float2(a0, a1);
    ((float2*)(ra + cb))[1] = make_float2(a2, a3);
    ((float2*)(ra + cb))[2] = make_float2(a4, a5);
    ((float2*)(rb + cb))[0] = make_float2(b0, b1);
    ((float2*)(rb + cb))[1] = make_float2(b2, b3);
    ((float2*)(rb + cb))[2] = make_float2(b4, b5);
}

__global__ void __launch_bounds__(WPB * 32)
StructureEncoder1D_kernel(const float* __restrict__ x,
                          const float* __restrict__ W1,
                          const float* __restrict__ b1,
                          const float* __restrict__ W2,
                          const float* __restrict__ b2,
                          float* __restrict__ out, int B) {
    extern __shared__ __align__(16) char dynsmem[];
    float* sw    = reinterpret_cast<float*>(dynsmem);                // non-dup weights
    char*  wbase = dynsmem + SW_BYTES;

    // ---- cooperative weight fill (plain floats, rows of 8) ----
    for (int i = threadIdx.x; i < NJ * JWF; i += blockDim.x) {
        int j = i / JWF, r = i % JWF, row = r >> 3, c = r & 7;
        float v;
        if (row < 7) {
            v = (c < 7) ? W1[j * 49 + row * 7 + c] : b1[j * 7 + row];
        } else {
            int rr = row - 7;
            v = (c < 7) ? W2[j * 42 + rr * 7 + c] : b2[j * 6 + rr];
        }
        sw[i] = v;
    }
    __syncthreads();

    const int lane   = threadIdx.x & 31;
    const int warpId = threadIdx.x >> 5;
    const int warpBase = (blockIdx.x * WPB + warpId) * 64;
    if (warpBase >= B) return;

    char* wb = wbase + warpId * WARP_BYTES;
    ull*   xs   = reinterpret_cast<ull*>(wb);
    float* tile = reinterpret_cast<float*>(wb + XS_ULL * 8);

    // ---- stage x: coalesced LDG.128 -> tile region (row stride 25 floats) ----
    {
        const float4* xin = reinterpret_cast<const float4*>(x);
#pragma unroll
        for (int k = 0; k < 12; ++k) {
            int i = k * 32 + lane;               // [0,384): 64 rows x 6 float4
            int r = i / 6, c = i % 6;
            float4 v = make_float4(0.f, 0.f, 0.f, 0.f);
            if (warpBase + r < B) v = xin[(size_t)(warpBase + r) * 6 + c];
            float* d = tile + r * 25 + c * 4;
            d[0] = v.x; d[1] = v.y; d[2] = v.z; d[3] = v.w;
        }
    }
    __syncwarp();

    // ---- build packed-x in xs: xs[j*32+lane] = {x[e0][j], x[e1][j]} ----
#pragma unroll
    for (int j = 0; j < 24; ++j) {
        float a = tile[lane * 25 + j];
        float b = tile[(lane + 32) * 25 + j];
        xs[j * 32 + lane] = pack2(a, b);
    }
    __syncwarp();

    float* ta = tile + lane * TPAD;          // even offset -> aligned float2
    float* tb = tile + (lane + 32) * TPAD;

    ull fA[6], fB[6], fC[6];

#define XP(J) (xs[(J) * 32 + lane])
#define WP(J) (reinterpret_cast<const float4*>(sw) + (J) * 26)
#define ST(F, CB) store6(F, ta, tb, CB)

    // flush quarter tile: 64 rows x 36 cols -> out cols [G*36, G*36+36)
#define FLUSH(G) do {                                                          \
        __syncwarp();                                                          \
        _Pragma("unroll")                                                      \
        for (int k = 0; k < 18; ++k) {                                         \
            int i = k * 32 + lane;               /* [0,576): 64 rows x 9 f4 */ \
            int r = i / 9, c = i % 9;                                          \
            if (warpBase + r < B) {                                            \
                const float2* s = reinterpret_cast<const float2*>(             \
                    tile + r * TPAD + c * 4);                                  \
                float2 lo = s[0], hi = s[1];                                   \
                *reinterpret_cast<float4*>(                                    \
                    out + (size_t)(warpBase + r) * 144 + (G) * 36 + c * 4) =   \
                    make_float4(lo.x, lo.y, hi.x, hi.y);                       \
            }                                                                  \
        }                                                                      \
        __syncwarp();                                                          \
    } while (0)

    // ---- phase 0: joints {0..5}, local col = j*6 ----
    root_fwd (WP(0), XP(0),      fA);  ST(fA, 0 * 6);   // fA = f0
    joint_fwd(WP(1), XP(1), fA,  fB);  ST(fB, 1 * 6);   // fB = f1
    joint_fwd(WP(4), XP(4), fB,  fB);  ST(fB, 4 * 6);   // fB = f4
    joint_fwd(WP(2), XP(2), fA,  fC);  ST(fC, 2 * 6);   // fC = f2
    joint_fwd(WP(5), XP(5), fC,  fC);  ST(fC, 5 * 6);   // fC = f5
    joint_fwd(WP(3), XP(3), fA,  fA);  ST(fA, 3 * 6);   // fA = f3
    FLUSH(0);

    // ---- phase 1: joints {6..11}, local col = (j-6)*6  (fA=f3, fB=f4, fC=f5) ----
    joint_fwd(WP(6),  XP(6),  fA, fA); ST(fA, 0 * 6);   // fA = f6
    joint_fwd(WP(9),  XP(9),  fA, fA); ST(fA, 3 * 6);   // fA = f9
    joint_fwd(WP(7),  XP(7),  fB, fB); ST(fB, 1 * 6);   // fB = f7
    joint_fwd(WP(10), XP(10), fB, fB); ST(fB, 4 * 6);   // f10 (leaf)
    joint_fwd(WP(8),  XP(8),  fC, fC); ST(fC, 2 * 6);   // fC = f8
    joint_fwd(WP(11), XP(11), fC, fC); ST(fC, 5 * 6);   // f11 (leaf)
    FLUSH(1);

    // ---- phase 2: joints {12..17}, local col = (j-12)*6  (fA=f9) ----
    joint_fwd(WP(12), XP(12), fA, fB); ST(fB, 0 * 6);   // fB = f12
    joint_fwd(WP(15), XP(15), fB, fB); ST(fB, 3 * 6);   // f15 (leaf)
    joint_fwd(WP(13), XP(13), fA, fB); ST(fB, 1 * 6);   // fB = f13
    joint_fwd(WP(16), XP(16), fB, fB); ST(fB, 4 * 6);   // fB = f16 (keep)
    joint_fwd(WP(14), XP(14), fA, fC); ST(fC, 2 * 6);   // fC = f14
    joint_fwd(WP(17), XP(17), fC, fC); ST(fC, 5 * 6);   // fC = f17 (keep)
    FLUSH(2);

    // ---- phase 3: joints {18..23}, local col = (j-18)*6  (fB=f16, fC=f17) ----
    joint_fwd(WP(18), XP(18), fB, fB); ST(fB, 0 * 6);   // fB = f18
    joint_fwd(WP(20), XP(20), fB, fB); ST(fB, 2 * 6);   // fB = f20
    joint_fwd(WP(22), XP(22), fB, fB); ST(fB, 4 * 6);   // f22 (leaf)
    joint_fwd(WP(19), XP(19), fC, fC); ST(fC, 1 * 6);   // fC = f19
    joint_fwd(WP(21), XP(21), fC, fC); ST(fC, 3 * 6);   // fC = f21
    joint_fwd(WP(23), XP(23), fC, fC); ST(fC, 5 * 6);   // f23 (leaf)
    FLUSH(3);

#undef XP
#undef WP
#undef ST
#undef FLUSH
}

extern "C" void kernel_launch(void* const* d_in, const int* in_sizes, int n_in,
                              void* d_out, int out_size) {
    const float* x  = (const float*)d_in[0];
    const float* W1 = (const float*)d_in[1];
    const float* b1 = (const float*)d_in[2];
    const float* W2 = (const float*)d_in[3];
    const float* b2 = (const float*)d_in[4];
    float* out = (float*)d_out;

    int B = in_sizes[0] / 24;
    int warps  = (B + 63) / 64;
    int blocks = (warps + WPB - 1) / WPB;

    cudaFuncSetAttribute(StructureEncoder1D_kernel,
                         cudaFuncAttributeMaxDynamicSharedMemorySize, SMEM_BYTES);
    StructureEncoder1D_kernel<<<blocks, WPB * 32, SMEM_BYTES>>>(x, W1, b1, W2, b2, out, B);
}